// round 2
// baseline (speedup 1.0000x reference)
#include <cuda_runtime.h>

#define N    4096
#define IT   30
#define G    128            // persistent blocks (<= SM count, co-resident)
#define TPB  512
#define NF4  (N / 4)        // 1024 float4 per row; also number of 4-row groups
#define TOTF4 ((size_t)N * N / 4)

// Scratch (__device__ globals: allocation-free rule)
static __device__ float g_B0[(size_t)N * N];   // (mean+std*eps)*log2(e)/TAU
static __device__ float g_r[N];
static __device__ float g_c[N];
static __device__ float g_part[(size_t)G * N]; // [block][col] column partials
static __device__ unsigned g_arrive;           // barrier (0-init, self-resetting)
static __device__ unsigned g_gen;              // barrier generation (monotonic)

// Lightweight grid-wide barrier (all G blocks co-resident by construction).
__device__ __forceinline__ void grid_bar() {
    __syncthreads();
    if (threadIdx.x == 0) {
        __threadfence();
        unsigned gen = *((volatile unsigned*)&g_gen);
        if (atomicAdd(&g_arrive, 1u) == (unsigned)G - 1u) {
            g_arrive = 0u;
            __threadfence();
            *((volatile unsigned*)&g_gen) = gen + 1u;
        } else {
            while (*((volatile unsigned*)&g_gen) == gen) { }
        }
        __threadfence();
    }
    __syncthreads();
}

__global__ void __launch_bounds__(TPB, 1)
sinkhorn_persistent(const float* __restrict__ eps,
                    const float* __restrict__ mean,
                    const float* __restrict__ stdv,
                    float* __restrict__ out) {
    const int b = blockIdx.x;
    const int t = threadIdx.x;
    const unsigned gtid = b * TPB + t;

    // ---------------- Phase 0: setup -------------------------------------
    {
        const float SCALE = 0.72134752044448170368f;  // log2(e)/TAU, TAU=2
        const float4* e4 = (const float4*)eps;
        const float4* m4 = (const float4*)mean;
        const float4* s4 = (const float4*)stdv;
        float4* b4 = (float4*)g_B0;
        for (size_t i = gtid; i < TOTF4; i += (size_t)G * TPB) {
            float4 e = e4[i], m = m4[i], s = s4[i];
            float4 o;
            o.x = (m.x + s.x * e.x) * SCALE;
            o.y = (m.y + s.y * e.y) * SCALE;
            o.z = (m.z + s.z * e.z) * SCALE;
            o.w = (m.w + s.w * e.w) * SCALE;
            b4[i] = o;
        }
        // zero r and c (must reset every launch: globals persist across replays)
        float4 z = make_float4(0.f, 0.f, 0.f, 0.f);
        if (gtid < 1024)                      ((float4*)g_c)[gtid] = z;
        else if (gtid < 2048)                 ((float4*)g_r)[gtid - 1024] = z;
    }
    grid_bar();

    __shared__ float4 red[16];

    // Thread owns fixed columns: float4 slots t and t+512
    //   -> cols [4t..4t+3] and [2048+4t..2048+4t+3]
    for (int it = 0; it < IT; it++) {
        float4 cA = __ldcg(((const float4*)g_c) + t);
        float4 cB = __ldcg(((const float4*)g_c) + t + 512);
        float acc[8];
        #pragma unroll
        for (int k = 0; k < 8; k++) acc[k] = 0.f;

        // -------- row phase: 4 rows per group, 8 groups per block --------
        #pragma unroll 1
        for (int g = b; g < NF4; g += G) {
            const int i0 = g * 4;
            float e[4][8];
            float rp[4], p[4];
            #pragma unroll
            for (int r = 0; r < 4; r++) {
                rp[r] = __ldcg(g_r + i0 + r);
                const float4* row4 = (const float4*)(g_B0 + (size_t)(i0 + r) * N);
                float4 a  = __ldcg(row4 + t);
                float4 bb = __ldcg(row4 + t + 512);
                e[r][0] = exp2f(a.x  - cA.x - rp[r]);
                e[r][1] = exp2f(a.y  - cA.y - rp[r]);
                e[r][2] = exp2f(a.z  - cA.z - rp[r]);
                e[r][3] = exp2f(a.w  - cA.w - rp[r]);
                e[r][4] = exp2f(bb.x - cB.x - rp[r]);
                e[r][5] = exp2f(bb.y - cB.y - rp[r]);
                e[r][6] = exp2f(bb.z - cB.z - rp[r]);
                e[r][7] = exp2f(bb.w - cB.w - rp[r]);
                p[r] = ((e[r][0] + e[r][1]) + (e[r][2] + e[r][3]))
                     + ((e[r][4] + e[r][5]) + (e[r][6] + e[r][7]));
            }
            // block-wide sum of p[0..3]
            #pragma unroll
            for (int o = 16; o > 0; o >>= 1) {
                p[0] += __shfl_xor_sync(0xffffffffu, p[0], o);
                p[1] += __shfl_xor_sync(0xffffffffu, p[1], o);
                p[2] += __shfl_xor_sync(0xffffffffu, p[2], o);
                p[3] += __shfl_xor_sync(0xffffffffu, p[3], o);
            }
            if ((t & 31) == 0) red[t >> 5] = make_float4(p[0], p[1], p[2], p[3]);
            __syncthreads();
            float4 S = red[0];
            #pragma unroll
            for (int w = 1; w < 16; w++) {
                float4 q = red[w];
                S.x += q.x; S.y += q.y; S.z += q.z; S.w += q.w;
            }
            // r update (exact LSE w.r.t. fixed shift rp): r_new = rp + log2(S)
            if (t == 0) {
                g_r[i0 + 0] = rp[0] + log2f(S.x);
                g_r[i0 + 1] = rp[1] + log2f(S.y);
                g_r[i0 + 2] = rp[2] + log2f(S.z);
                g_r[i0 + 3] = rp[3] + log2f(S.w);
            }
            // column contribution: 2^(B0 - c_prev - r_new) = e / S  (free!)
            float sc0 = __fdividef(1.f, S.x);
            float sc1 = __fdividef(1.f, S.y);
            float sc2 = __fdividef(1.f, S.z);
            float sc3 = __fdividef(1.f, S.w);
            #pragma unroll
            for (int k = 0; k < 8; k++) {
                acc[k] += e[0][k] * sc0;
                acc[k] += e[1][k] * sc1;
                acc[k] += e[2][k] * sc2;
                acc[k] += e[3][k] * sc3;
            }
            __syncthreads();   // protect red[] reuse next group
        }

        // -------- write column partials (coalesced, [block][col]) --------
        {
            float4* pp = (float4*)(g_part + (size_t)b * N);
            pp[t]       = make_float4(acc[0], acc[1], acc[2], acc[3]);
            pp[t + 512] = make_float4(acc[4], acc[5], acc[6], acc[7]);
        }
        grid_bar();

        // -------- combine: warp 0 of each block owns 32 columns ----------
        if (t < 32) {
            const int col = b * 32 + t;
            float sum = 0.f;
            #pragma unroll 8
            for (int k = 0; k < G; k++)
                sum += __ldcg(g_part + (size_t)k * N + col);
            g_c[col] = __ldcg(g_c + col) + log2f(sum);
        }
        grid_bar();
    }

    // ---------------- Final: out = 2^(B0 - r(i) - c(j)) ------------------
    {
        const float4* b4 = (const float4*)g_B0;
        float4* o4 = (float4*)out;
        for (size_t i = gtid; i < TOTF4; i += (size_t)G * TPB) {
            int row = (int)(i >> 10);        // 1024 float4 per row
            int cf  = (int)(i & 1023);
            float rv  = __ldcg(g_r + row);
            float4 cv = __ldcg(((const float4*)g_c) + cf);
            float4 bb = b4[i];
            float4 o;
            o.x = exp2f(bb.x - rv - cv.x);
            o.y = exp2f(bb.y - rv - cv.y);
            o.z = exp2f(bb.z - rv - cv.z);
            o.w = exp2f(bb.w - rv - cv.w);
            o4[i] = o;
        }
    }
}

extern "C" void kernel_launch(void* const* d_in, const int* in_sizes, int n_in,
                              void* d_out, int out_size) {
    const float* eps  = (const float*)d_in[0];
    const float* mean = (const float*)d_in[1];
    const float* stdv = (const float*)d_in[2];
    sinkhorn_persistent<<<G, TPB>>>(eps, mean, stdv, (float*)d_out);
}